// round 15
// baseline (speedup 1.0000x reference)
#include <cuda_runtime.h>
#include <cuda_bf16.h>
#include <math.h>
#include <stdint.h>

#define NN 100000
#define EE 1600000

// ---------------- static scratch ----------------
__device__ float g_h1[NN * 128];
__device__ float g_res[NN * 128];
__device__ float g_asrc1[NN * 8];
__device__ float g_adst1[NN * 8];
__device__ float g_h2[NN * 64];
__device__ float g_asrc2[NN];
__device__ float g_adst2[NN];
__device__ __nv_bfloat16 g_b1hi[256 * 128];
__device__ __nv_bfloat16 g_b1lo[256 * 128];
__device__ __nv_bfloat16 g_b2hi[64 * 128];
__device__ __nv_bfloat16 g_b2lo[64 * 128];
__device__ int g_cnt[NN];
__device__ int g_rowptr[NN + 1];
__device__ int g_blocksums[128];
__device__ int g_csr[EE];

// ---------------- helpers ----------------
__device__ __forceinline__ float lrelu_exp(float v) {
    float e = v > 0.0f ? v : 0.2f * v;
    return __expf(e);
}
__device__ __forceinline__ float warp_sum(float v) {
    #pragma unroll
    for (int o = 16; o > 0; o >>= 1) v += __shfl_xor_sync(0xffffffffu, v, o);
    return v;
}
__device__ __forceinline__ uint32_t smem_u32(const void* p) {
    uint32_t a;
    asm("{ .reg .u64 t; cvta.to.shared.u64 t, %1; cvt.u32.u64 %0, t; }" : "=r"(a) : "l"(p));
    return a;
}
__device__ __forceinline__ void ldsm4(uint32_t* r, uint32_t addr) {
    asm volatile("ldmatrix.sync.aligned.m8n8.x4.shared.b16 {%0,%1,%2,%3}, [%4];"
                 : "=r"(r[0]), "=r"(r[1]), "=r"(r[2]), "=r"(r[3]) : "r"(addr));
}
__device__ __forceinline__ void mma16816(float* c, const uint32_t* a, uint32_t b0, uint32_t b1) {
    asm volatile(
        "mma.sync.aligned.m16n8k16.row.col.f32.bf16.bf16.f32 "
        "{%0,%1,%2,%3}, {%4,%5,%6,%7}, {%8,%9}, {%0,%1,%2,%3};"
        : "+f"(c[0]), "+f"(c[1]), "+f"(c[2]), "+f"(c[3])
        : "r"(a[0]), "r"(a[1]), "r"(a[2]), "r"(a[3]), "r"(b0), "r"(b1));
}
__device__ __forceinline__ void cpa16(uint32_t smem, const void* g) {
    asm volatile("cp.async.cg.shared.global [%0], [%1], 16;" :: "r"(smem), "l"(g));
}
__device__ __forceinline__ void split_store(float v, __nv_bfloat16* hi, __nv_bfloat16* lo) {
    __nv_bfloat16 h = __float2bfloat16_rn(v);
    *hi = h;
    *lo = __float2bfloat16_rn(v - __bfloat162float(h));
}

// ---------------- prep_b: B images only (runs on main stream) ----------------------
__global__ void __launch_bounds__(256) prep_b(const float* __restrict__ W1,
                                              const float* __restrict__ resW,
                                              const float* __restrict__ W2) {
    int b = blockIdx.x, tid = threadIdx.x;
    if (b < 128) {
        int idx = b * 256 + tid;
        int nn = idx >> 7, k = idx & 127;
        float w = (nn < 128) ? W1[k * 128 + nn] : resW[k * 128 + (nn - 128)];
        split_store(w, &g_b1hi[nn * 128 + k], &g_b1lo[nn * 128 + k]);
    } else {
        int idx = (b - 128) * 256 + tid;
        int nn = idx >> 7, k = idx & 127;
        split_store(W2[k * 64 + nn], &g_b2hi[nn * 128 + k], &g_b2lo[nn * 128 + k]);
    }
}

__global__ void zero_cnt(int n) {
    int i = blockIdx.x * blockDim.x + threadIdx.x;
    if (i < n) g_cnt[i] = 0;
}

// ---------------- persistent-slab HMMA GEMM (layer 1) + fused att dots -------------
#define RS 136
#define A_ST (128 * RS)
#define B_ST (64 * RS)
#define SMEMB ((2 * A_ST + 2 * B_ST) * 2)   // 104448 bytes -> 2 CTAs/SM

__global__ void __launch_bounds__(256) gemm1(const float* __restrict__ A,
                                             const __nv_bfloat16* __restrict__ Bhi,
                                             const __nv_bfloat16* __restrict__ Blo,
                                             float* __restrict__ C0,
                                             float* __restrict__ C1,
                                             const float* __restrict__ att_src,
                                             const float* __restrict__ att_dst,
                                             int M) {
    extern __shared__ __nv_bfloat16 smp[];
    const uint32_t sb = smem_u32(smp);
    const uint32_t sbAh = sb, sbAl = sb + A_ST * 2;
    const uint32_t sbBh = sb + 2 * A_ST * 2, sbBl = sb + (2 * A_ST + B_ST) * 2;

    const int tid = threadIdx.x;
    const int wid = tid >> 5, lane = tid & 31;
    const int m0 = blockIdx.x * 128;

    auto issue_B = [&](int slab) {
        const __nv_bfloat16* bh = Bhi + (size_t)slab * 64 * 128;
        const __nv_bfloat16* bl = Blo + (size_t)slab * 64 * 128;
        #pragma unroll
        for (int it = 0; it < 4; it++) {
            int idx = tid + it * 256;
            int row = idx >> 4;
            int seg = (idx & 15) * 8;
            uint32_t so = (uint32_t)(row * RS + seg) * 2;
            cpa16(sbBh + so, bh + row * 128 + seg);
            cpa16(sbBl + so, bl + row * 128 + seg);
        }
        asm volatile("cp.async.commit_group;" ::: "memory");
    };

    issue_B(0);

    #pragma unroll
    for (int it = 0; it < 16; it++) {
        int idx = tid + it * 256;
        int row = idx >> 5;
        int colq = (idx & 31) * 4;
        float4 v = make_float4(0.f, 0.f, 0.f, 0.f);
        if (m0 + row < M) v = *(const float4*)(A + (size_t)(m0 + row) * 128 + colq);
        __nv_bfloat16 h0 = __float2bfloat16_rn(v.x), h1 = __float2bfloat16_rn(v.y);
        __nv_bfloat16 h2 = __float2bfloat16_rn(v.z), h3 = __float2bfloat16_rn(v.w);
        __nv_bfloat16 l0 = __float2bfloat16_rn(v.x - __bfloat162float(h0));
        __nv_bfloat16 l1 = __float2bfloat16_rn(v.y - __bfloat162float(h1));
        __nv_bfloat16 l2 = __float2bfloat16_rn(v.z - __bfloat162float(h2));
        __nv_bfloat16 l3 = __float2bfloat16_rn(v.w - __bfloat162float(h3));
        int o = row * RS + colq;
        *(__nv_bfloat162*)&smp[o]            = __halves2bfloat162(h0, h1);
        *(__nv_bfloat162*)&smp[o + 2]        = __halves2bfloat162(h2, h3);
        *(__nv_bfloat162*)&smp[A_ST + o]     = __halves2bfloat162(l0, l1);
        *(__nv_bfloat162*)&smp[A_ST + o + 2] = __halves2bfloat162(l2, l3);
    }
    asm volatile("cp.async.wait_group 0;" ::: "memory");
    __syncthreads();

    const int wm = wid >> 1;
    const int wn = wid & 1;

    #pragma unroll
    for (int slab = 0; slab < 4; slab++) {
        float acc[2][4][4] = {};

        #pragma unroll
        for (int kk = 0; kk < 8; kk++) {
            uint32_t ah[2][4], alr[2][4];
            #pragma unroll
            for (int mt = 0; mt < 2; mt++) {
                uint32_t r = wm * 32 + mt * 16 + (lane & 15);
                uint32_t c = kk * 16 + (lane >> 4) * 8;
                uint32_t off = (r * RS + c) * 2;
                ldsm4(ah[mt], sbAh + off);
                ldsm4(alr[mt], sbAl + off);
            }
            uint32_t bh[2][4], bl[2][4];
            #pragma unroll
            for (int ld = 0; ld < 2; ld++) {
                uint32_t nrow = wn * 32 + ld * 16 + ((lane >> 4) & 1) * 8 + (lane & 7);
                uint32_t c = kk * 16 + ((lane >> 3) & 1) * 8;
                uint32_t off = (nrow * RS + c) * 2;
                ldsm4(bh[ld], sbBh + off);
                ldsm4(bl[ld], sbBl + off);
            }
            #pragma unroll
            for (int mt = 0; mt < 2; mt++)
                #pragma unroll
                for (int nt = 0; nt < 4; nt++) {
                    uint32_t b0h = bh[nt >> 1][(nt & 1) * 2], b1h = bh[nt >> 1][(nt & 1) * 2 + 1];
                    uint32_t b0l = bl[nt >> 1][(nt & 1) * 2], b1l = bl[nt >> 1][(nt & 1) * 2 + 1];
                    mma16816(acc[mt][nt], ah[mt], b0h, b1h);
                    mma16816(acc[mt][nt], ah[mt], b0l, b1l);
                    mma16816(acc[mt][nt], alr[mt], b0h, b1h);
                }
        }
        __syncthreads();
        if (slab + 1 < 4) issue_B(slab + 1);

        float* Cp;
        int coloff;
        if (slab < 2) { Cp = C0; coloff = slab * 64; }
        else { Cp = C1; coloff = (slab - 2) * 64; }

        #pragma unroll
        for (int mt = 0; mt < 2; mt++)
            #pragma unroll
            for (int nt = 0; nt < 4; nt++) {
                int row = m0 + wm * 32 + mt * 16 + (lane >> 2);
                int col = coloff + wn * 32 + nt * 8 + (lane & 3) * 2;
                if (row < M)
                    *(float2*)&Cp[(size_t)row * 128 + col] = make_float2(acc[mt][nt][0], acc[mt][nt][1]);
                if (row + 8 < M)
                    *(float2*)&Cp[(size_t)(row + 8) * 128 + col] = make_float2(acc[mt][nt][2], acc[mt][nt][3]);
            }

        if (slab < 2) {
            #pragma unroll
            for (int mt = 0; mt < 2; mt++) {
                #pragma unroll
                for (int hh = 0; hh < 2; hh++) {
                    int head = slab * 4 + wn * 2 + hh;
                    float ps0 = 0.f, pd0 = 0.f, ps1 = 0.f, pd1 = 0.f;
                    #pragma unroll
                    for (int q = 0; q < 2; q++) {
                        int nt = hh * 2 + q;
                        int cih = q * 8 + (lane & 3) * 2;
                        float a0 = att_src[head * 16 + cih], a1 = att_src[head * 16 + cih + 1];
                        float d0 = att_dst[head * 16 + cih], d1 = att_dst[head * 16 + cih + 1];
                        ps0 += acc[mt][nt][0] * a0 + acc[mt][nt][1] * a1;
                        pd0 += acc[mt][nt][0] * d0 + acc[mt][nt][1] * d1;
                        ps1 += acc[mt][nt][2] * a0 + acc[mt][nt][3] * a1;
                        pd1 += acc[mt][nt][2] * d0 + acc[mt][nt][3] * d1;
                    }
                    #pragma unroll
                    for (int o = 1; o <= 2; o <<= 1) {
                        ps0 += __shfl_xor_sync(0xffffffffu, ps0, o);
                        pd0 += __shfl_xor_sync(0xffffffffu, pd0, o);
                        ps1 += __shfl_xor_sync(0xffffffffu, ps1, o);
                        pd1 += __shfl_xor_sync(0xffffffffu, pd1, o);
                    }
                    if ((lane & 3) == 0) {
                        int r0 = m0 + wm * 32 + mt * 16 + (lane >> 2);
                        if (r0 < M)     { g_asrc1[r0 * 8 + head] = ps0;       g_adst1[r0 * 8 + head] = pd0; }
                        if (r0 + 8 < M) { g_asrc1[(r0 + 8) * 8 + head] = ps1; g_adst1[(r0 + 8) * 8 + head] = pd1; }
                    }
                }
            }
        }

        if (slab + 1 < 4) {
            asm volatile("cp.async.wait_group 0;" ::: "memory");
            __syncthreads();
        }
    }
}

// ---------------- fused: layer-1 aggregation + LN + ELU + layer-2 GEMM -------------
// grid = mblocks; each CTA: 8 warps x 16 nodes agg -> h (fp32 to out, bf16 hi/lo to
// smem A) -> MODE-2 HMMA mainloop (h @ W2) + layer-2 att-dot epilogue.
__global__ void __launch_bounds__(256) agg_gemm2(const float* __restrict__ bias1,
                                                 const float* __restrict__ gamma,
                                                 const float* __restrict__ beta,
                                                 const __nv_bfloat16* __restrict__ Bhi,
                                                 const __nv_bfloat16* __restrict__ Blo,
                                                 const float* __restrict__ att_src,
                                                 const float* __restrict__ att_dst,
                                                 float* __restrict__ out, int n) {
    extern __shared__ __nv_bfloat16 smp[];
    const uint32_t sb = smem_u32(smp);
    const uint32_t sbAh = sb, sbAl = sb + A_ST * 2;
    const uint32_t sbBh = sb + 2 * A_ST * 2, sbBl = sb + (2 * A_ST + B_ST) * 2;

    const int tid = threadIdx.x;
    const int wid = tid >> 5, lane = tid & 31;
    const int m0 = blockIdx.x * 128;
    const int head = lane >> 2;

    // start B2 load immediately (overlaps the whole agg phase)
    {
        #pragma unroll
        for (int it = 0; it < 4; it++) {
            int idx = tid + it * 256;
            int row = idx >> 4;
            int seg = (idx & 15) * 8;
            uint32_t so = (uint32_t)(row * RS + seg) * 2;
            cpa16(sbBh + so, Bhi + row * 128 + seg);
            cpa16(sbBl + so, Blo + row * 128 + seg);
        }
        asm volatile("cp.async.commit_group;" ::: "memory");
    }

    // ---- phase 1: aggregate 16 nodes per warp ----
    for (int r = 0; r < 16; r++) {
        int row = wid * 16 + r;
        int i = m0 + row;
        if (i >= n) break;
        float ad = g_adst1[i * 8 + head];
        // early residual prefetch
        float4 rv = *(const float4*)&g_res[(size_t)i * 128 + lane * 4];

        float4 acc;
        float denom;
        {
            float p = lrelu_exp(g_asrc1[i * 8 + head] + ad);
            float4 v = *(const float4*)&g_h1[(size_t)i * 128 + lane * 4];
            acc = make_float4(p * v.x, p * v.y, p * v.z, p * v.w);
            denom = p;
        }
        int start = g_rowptr[i], end = g_rowptr[i + 1];
        int j = start;
        for (; j + 4 <= end; j += 4) {
            int s0 = g_csr[j], s1 = g_csr[j + 1], s2 = g_csr[j + 2], s3 = g_csr[j + 3];
            float p0 = lrelu_exp(g_asrc1[s0 * 8 + head] + ad);
            float p1 = lrelu_exp(g_asrc1[s1 * 8 + head] + ad);
            float p2 = lrelu_exp(g_asrc1[s2 * 8 + head] + ad);
            float p3 = lrelu_exp(g_asrc1[s3 * 8 + head] + ad);
            float4 v0 = *(const float4*)&g_h1[(size_t)s0 * 128 + lane * 4];
            float4 v1 = *(const float4*)&g_h1[(size_t)s1 * 128 + lane * 4];
            float4 v2 = *(const float4*)&g_h1[(size_t)s2 * 128 + lane * 4];
            float4 v3 = *(const float4*)&g_h1[(size_t)s3 * 128 + lane * 4];
            acc.x += p0 * v0.x + p1 * v1.x + p2 * v2.x + p3 * v3.x;
            acc.y += p0 * v0.y + p1 * v1.y + p2 * v2.y + p3 * v3.y;
            acc.z += p0 * v0.z + p1 * v1.z + p2 * v2.z + p3 * v3.z;
            acc.w += p0 * v0.w + p1 * v1.w + p2 * v2.w + p3 * v3.w;
            denom += p0 + p1 + p2 + p3;
        }
        for (; j < end; j++) {
            int s = g_csr[j];
            float p = lrelu_exp(g_asrc1[s * 8 + head] + ad);
            float4 v = *(const float4*)&g_h1[(size_t)s * 128 + lane * 4];
            acc.x += p * v.x; acc.y += p * v.y; acc.z += p * v.z; acc.w += p * v.w;
            denom += p;
        }
        float inv = __fdividef(1.0f, denom + 1e-16f);
        float4 bv = *(const float4*)&bias1[lane * 4];
        float4 v;
        v.x = acc.x * inv + bv.x + rv.x;
        v.y = acc.y * inv + bv.y + rv.y;
        v.z = acc.z * inv + bv.z + rv.z;
        v.w = acc.w * inv + bv.w + rv.w;
        float mu = warp_sum(v.x + v.y + v.z + v.w) * (1.0f / 128.0f);
        float dx = v.x - mu, dy = v.y - mu, dz = v.z - mu, dw = v.w - mu;
        float var = warp_sum(dx * dx + dy * dy + dz * dz + dw * dw) * (1.0f / 128.0f);
        float rs = rsqrtf(var + 1e-5f);
        float4 g4 = *(const float4*)&gamma[lane * 4];
        float4 b4 = *(const float4*)&beta[lane * 4];
        float4 o;
        o.x = dx * rs * g4.x + b4.x;
        o.y = dy * rs * g4.y + b4.y;
        o.z = dz * rs * g4.z + b4.z;
        o.w = dw * rs * g4.w + b4.w;
        o.x = o.x > 0.f ? o.x : expm1f(o.x);
        o.y = o.y > 0.f ? o.y : expm1f(o.y);
        o.z = o.z > 0.f ? o.z : expm1f(o.z);
        o.w = o.w > 0.f ? o.w : expm1f(o.w);
        *(float4*)(out + (size_t)i * 128 + lane * 4) = o;

        // store bf16 hi/lo into smem A for the layer-2 GEMM
        __nv_bfloat16 h0 = __float2bfloat16_rn(o.x), h1 = __float2bfloat16_rn(o.y);
        __nv_bfloat16 h2 = __float2bfloat16_rn(o.z), h3 = __float2bfloat16_rn(o.w);
        __nv_bfloat16 l0 = __float2bfloat16_rn(o.x - __bfloat162float(h0));
        __nv_bfloat16 l1 = __float2bfloat16_rn(o.y - __bfloat162float(h1));
        __nv_bfloat16 l2 = __float2bfloat16_rn(o.z - __bfloat162float(h2));
        __nv_bfloat16 l3 = __float2bfloat16_rn(o.w - __bfloat162float(h3));
        int so = row * RS + lane * 4;
        *(__nv_bfloat162*)&smp[so]            = __halves2bfloat162(h0, h1);
        *(__nv_bfloat162*)&smp[so + 2]        = __halves2bfloat162(h2, h3);
        *(__nv_bfloat162*)&smp[A_ST + so]     = __halves2bfloat162(l0, l1);
        *(__nv_bfloat162*)&smp[A_ST + so + 2] = __halves2bfloat162(l2, l3);
    }
    // zero A rows beyond n (last block only) to keep mma inputs finite
    if (m0 + 128 > n) {
        for (int row = n - m0 < 0 ? 0 : n - m0; row < 128; row += 1) {
            for (int c = tid; c < 64; c += 256) {
                *(uint32_t*)&smp[row * RS + c * 2] = 0;
                *(uint32_t*)&smp[A_ST + row * RS + c * 2] = 0;
            }
        }
    }
    asm volatile("cp.async.wait_group 0;" ::: "memory");
    __syncthreads();

    // ---- phase 2: h @ W2 mainloop + layer-2 att dots ----
    const int wm = wid >> 1;
    const int wn = wid & 1;
    float acc[2][4][4] = {};

    #pragma unroll
    for (int kk = 0; kk < 8; kk++) {
        uint32_t ah[2][4], alr[2][4];
        #pragma unroll
        for (int mt = 0; mt < 2; mt++) {
            uint32_t r = wm * 32 + mt * 16 + (lane & 15);
            uint32_t c = kk * 16 + (lane >> 4) * 8;
            uint32_t off = (r * RS + c) * 2;
            ldsm4(ah[mt], sbAh + off);
            ldsm4(alr[mt], sbAl + off);
        }
        uint32_t bh[2][4], bl[2][4];
        #pragma unroll
        for (int ld = 0; ld < 2; ld++) {
            uint32_t nrow = wn * 32 + ld * 16 + ((lane >> 4) & 1) * 8 + (lane & 7);
            uint32_t c = kk * 16 + ((lane >> 3) & 1) * 8;
            uint32_t off = (nrow * RS + c) * 2;
            ldsm4(bh[ld], sbBh + off);
            ldsm4(bl[ld], sbBl + off);
        }
        #pragma unroll
        for (int mt = 0; mt < 2; mt++)
            #pragma unroll
            for (int nt = 0; nt < 4; nt++) {
                uint32_t b0h = bh[nt >> 1][(nt & 1) * 2], b1h = bh[nt >> 1][(nt & 1) * 2 + 1];
                uint32_t b0l = bl[nt >> 1][(nt & 1) * 2], b1l = bl[nt >> 1][(nt & 1) * 2 + 1];
                mma16816(acc[mt][nt], ah[mt], b0h, b1h);
                mma16816(acc[mt][nt], ah[mt], b0l, b1l);
                mma16816(acc[mt][nt], alr[mt], b0h, b1h);
            }
    }
    __syncthreads();

    // C store (h2)
    #pragma unroll
    for (int mt = 0; mt < 2; mt++)
        #pragma unroll
        for (int nt = 0; nt < 4; nt++) {
            int row = m0 + wm * 32 + mt * 16 + (lane >> 2);
            int col = wn * 32 + nt * 8 + (lane & 3) * 2;
            if (row < n)
                *(float2*)&g_h2[(size_t)row * 64 + col] = make_float2(acc[mt][nt][0], acc[mt][nt][1]);
            if (row + 8 < n)
                *(float2*)&g_h2[(size_t)(row + 8) * 64 + col] = make_float2(acc[mt][nt][2], acc[mt][nt][3]);
        }

    // layer-2 att dots via smem reduce
    {
        float* sps = (float*)smp;
        float* spd = sps + 256;
        float ps[2][2] = {}, pd[2][2] = {};
        #pragma unroll
        for (int nt = 0; nt < 4; nt++) {
            int col = wn * 32 + nt * 8 + (lane & 3) * 2;
            float a0 = att_src[col], a1 = att_src[col + 1];
            float d0 = att_dst[col], d1 = att_dst[col + 1];
            #pragma unroll
            for (int mt = 0; mt < 2; mt++) {
                ps[mt][0] += acc[mt][nt][0] * a0 + acc[mt][nt][1] * a1;
                pd[mt][0] += acc[mt][nt][0] * d0 + acc[mt][nt][1] * d1;
                ps[mt][1] += acc[mt][nt][2] * a0 + acc[mt][nt][3] * a1;
                pd[mt][1] += acc[mt][nt][2] * d0 + acc[mt][nt][3] * d1;
            }
        }
        #pragma unroll
        for (int o = 1; o <= 2; o <<= 1)
            #pragma unroll
            for (int mt = 0; mt < 2; mt++)
                #pragma unroll
                for (int hf = 0; hf < 2; hf++) {
                    ps[mt][hf] += __shfl_xor_sync(0xffffffffu, ps[mt][hf], o);
                    pd[mt][hf] += __shfl_xor_sync(0xffffffffu, pd[mt][hf], o);
                }
        if ((lane & 3) == 0) {
            #pragma unroll
            for (int mt = 0; mt < 2; mt++)
                #pragma unroll
                for (int hf = 0; hf < 2; hf++) {
                    int rl = wm * 32 + mt * 16 + (lane >> 2) + hf * 8;
                    sps[rl * 2 + wn] = ps[mt][hf];
                    spd[rl * 2 + wn] = pd[mt][hf];
                }
        }
        __syncthreads();
        if (tid < 128) {
            int r = m0 + tid;
            if (r < n) {
                g_asrc2[r] = sps[tid * 2] + sps[tid * 2 + 1];
                g_adst2[r] = spd[tid * 2] + spd[tid * 2 + 1];
            }
        }
    }
}

// ---------------- CSR build --------------------------------------------------------
__global__ void count_k(const int* __restrict__ dst, int E) {
    int e = blockIdx.x * blockDim.x + threadIdx.x;
    if (e < E) atomicAdd(&g_cnt[dst[e]], 1);
}
__global__ void __launch_bounds__(1024) scan_blk(int n) {
    __shared__ int sm[1024];
    int tid = threadIdx.x;
    int i = blockIdx.x * 1024 + tid;
    int v = (i < n) ? g_cnt[i] : 0;
    sm[tid] = v;
    __syncthreads();
    #pragma unroll
    for (int off = 1; off < 1024; off <<= 1) {
        int t = (tid >= off) ? sm[tid - off] : 0;
        __syncthreads();
        sm[tid] += t;
        __syncthreads();
    }
    if (i < n) g_rowptr[i] = sm[tid] - v;
    if (tid == 1023) g_blocksums[blockIdx.x] = sm[1023];
}
__global__ void __launch_bounds__(128) scan_top(int nb) {
    __shared__ int sm[128];
    int tid = threadIdx.x;
    int v = (tid < nb) ? g_blocksums[tid] : 0;
    sm[tid] = v;
    __syncthreads();
    #pragma unroll
    for (int off = 1; off < 128; off <<= 1) {
        int t = (tid >= off) ? sm[tid - off] : 0;
        __syncthreads();
        sm[tid] += t;
        __syncthreads();
    }
    if (tid < nb) g_blocksums[tid] = sm[tid] - v;
}
__global__ void scan_add(int n, int E) {
    int i = blockIdx.x * blockDim.x + threadIdx.x;
    if (i < n) g_rowptr[i] += g_blocksums[i >> 10];
    if (i == 0) g_rowptr[n] = E;
}
__global__ void scatter_k(const int* __restrict__ src, const int* __restrict__ dst, int E) {
    int e = blockIdx.x * blockDim.x + threadIdx.x;
    if (e < E) {
        int d = dst[e];
        int old = atomicSub(&g_cnt[d], 1);
        g_csr[g_rowptr[d] + old - 1] = src[e];
    }
}

// ---------------- layer2 pull aggregation + finalize (warp per node) ---------------
__global__ void __launch_bounds__(256) agg_fin2(const float* __restrict__ bias2,
                                                float* __restrict__ out, int n) {
    int i = (blockIdx.x * blockDim.x + threadIdx.x) >> 5;
    int lane = threadIdx.x & 31;
    if (i >= n) return;
    float ad = g_adst2[i];

    float2 acc;
    float denom;
    {
        float p = lrelu_exp(g_asrc2[i] + ad);
        float2 v = *(const float2*)&g_h2[(size_t)i * 64 + lane * 2];
        acc = make_float2(p * v.x, p * v.y);
        denom = p;
    }
    int start = g_rowptr[i], end = g_rowptr[i + 1];

    int j = start;
    for (; j + 4 <= end; j += 4) {
        int s0 = g_csr[j], s1 = g_csr[j + 1], s2 = g_csr[j + 2], s3 = g_csr[j + 3];
        float p0 = lrelu_exp(g_asrc2[s0] + ad);
        float p1 = lrelu_exp(g_asrc2[s1] + ad);
        float p2 = lrelu_exp(g_asrc2[s2] + ad);
        float p3 = lrelu_exp(g_asrc2[s3] + ad);
        float2 v0 = *(const float2*)&g_h2[(size_t)s0 * 64 + lane * 2];
        float2 v1 = *(const float2*)&g_h2[(size_t)s1 * 64 + lane * 2];
        float2 v2 = *(const float2*)&g_h2[(size_t)s2 * 64 + lane * 2];
        float2 v3 = *(const float2*)&g_h2[(size_t)s3 * 64 + lane * 2];
        acc.x += p0 * v0.x + p1 * v1.x + p2 * v2.x + p3 * v3.x;
        acc.y += p0 * v0.y + p1 * v1.y + p2 * v2.y + p3 * v3.y;
        denom += p0 + p1 + p2 + p3;
    }
    for (; j < end; j++) {
        int s = g_csr[j];
        float p = lrelu_exp(g_asrc2[s] + ad);
        float2 v = *(const float2*)&g_h2[(size_t)s * 64 + lane * 2];
        acc.x += p * v.x; acc.y += p * v.y;
        denom += p;
    }
    float inv = __fdividef(1.0f, denom + 1e-16f);
    float2 bv = *(const float2*)&bias2[lane * 2];
    float2 o;
    o.x = acc.x * inv + bv.x;
    o.y = acc.y * inv + bv.y;
    *(float2*)(out + (size_t)n * 128 + (size_t)i * 64 + lane * 2) = o;
}

// ---------------- launch (dual-stream) ---------------------------------------------
extern "C" void kernel_launch(void* const* d_in, const int* in_sizes, int n_in,
                              void* d_out, int out_size) {
    const float* x        = (const float*)d_in[0];
    const int*   ei       = (const int*)d_in[1];
    const float* W1       = (const float*)d_in[2];
    const float* att_src1 = (const float*)d_in[3];
    const float* att_dst1 = (const float*)d_in[4];
    const float* bias1    = (const float*)d_in[5];
    const float* res_W    = (const float*)d_in[6];
    const float* gamma    = (const float*)d_in[7];
    const float* beta     = (const float*)d_in[8];
    const float* W2       = (const float*)d_in[9];
    const float* att_src2 = (const float*)d_in[10];
    const float* att_dst2 = (const float*)d_in[11];
    const float* bias2    = (const float*)d_in[12];
    float* out = (float*)d_out;

    int n = in_sizes[0] / 128;
    int E = in_sizes[1] / 2;
    if (n > NN) n = NN;
    if (E > EE) E = EE;
    const int* srcp = ei;
    const int* dstp = ei + E;

    float *p_h1, *p_res;
    __nv_bfloat16 *b1h, *b1l, *b2h, *b2l;
    cudaGetSymbolAddress((void**)&p_h1, g_h1);
    cudaGetSymbolAddress((void**)&p_res, g_res);
    cudaGetSymbolAddress((void**)&b1h, g_b1hi);
    cudaGetSymbolAddress((void**)&b1l, g_b1lo);
    cudaGetSymbolAddress((void**)&b2h, g_b2hi);
    cudaGetSymbolAddress((void**)&b2l, g_b2lo);

    cudaFuncSetAttribute(gemm1, cudaFuncAttributeMaxDynamicSharedMemorySize, SMEMB);
    cudaFuncSetAttribute(agg_gemm2, cudaFuncAttributeMaxDynamicSharedMemorySize, SMEMB);

    int nb = (n + 1023) / 1024;
    int mblocks = (n + 127) / 128;
    int nwarp_blocks = (n + 7) / 8;

    cudaStream_t s2;
    cudaEvent_t evFork, evJoin;
    cudaStreamCreateWithFlags(&s2, cudaStreamNonBlocking);
    cudaEventCreateWithFlags(&evFork, cudaEventDisableTiming);
    cudaEventCreateWithFlags(&evJoin, cudaEventDisableTiming);

    // ---- fork at t=0 ----
    cudaEventRecord(evFork, 0);
    cudaStreamWaitEvent(s2, evFork, 0);

    // side stream: full CSR chain (incl. zeroing)
    zero_cnt<<<(n + 255) / 256, 256, 0, s2>>>(n);
    count_k<<<(E + 255) / 256, 256, 0, s2>>>(dstp, E);
    scan_blk<<<nb, 1024, 0, s2>>>(n);
    scan_top<<<1, 128, 0, s2>>>(nb);
    scan_add<<<(n + 255) / 256, 256, 0, s2>>>(n, E);
    scatter_k<<<(E + 255) / 256, 256, 0, s2>>>(srcp, dstp, E);
    cudaEventRecord(evJoin, s2);

    // main stream: B images + layer-1 GEMM
    prep_b<<<160, 256>>>(W1, res_W, W2);
    gemm1<<<mblocks, 256, SMEMB>>>(x, b1h, b1l, p_h1, p_res, att_src1, att_dst1, n);

    // join: aggregation needs CSR too
    cudaStreamWaitEvent(0, evJoin, 0);

    // fused layer-1 aggregation + LN + ELU + layer-2 GEMM + att dots
    agg_gemm2<<<mblocks, 256, SMEMB>>>(bias1, gamma, beta, b2h, b2l,
                                       att_src2, att_dst2, out, n);
    // layer-2 aggregation -> logits
    agg_fin2<<<nwarp_blocks, 256>>>(bias2, out, n);
}

// round 16
// speedup vs baseline: 1.3645x; 1.3645x over previous
#include <cuda_runtime.h>
#include <cuda_bf16.h>
#include <math.h>
#include <stdint.h>

#define NN 100000
#define EE 1600000

// ---------------- static scratch ----------------
__device__ float g_h1[NN * 128];
__device__ float g_res[NN * 128];
__device__ float g_asrc1[NN * 8];
__device__ float g_adst1[NN * 8];
__device__ float g_h2[NN * 64];
__device__ float g_asrc2[NN];
__device__ float g_adst2[NN];
__device__ __nv_bfloat16 g_b1hi[256 * 128];
__device__ __nv_bfloat16 g_b1lo[256 * 128];
__device__ __nv_bfloat16 g_b2hi[64 * 128];
__device__ __nv_bfloat16 g_b2lo[64 * 128];
__device__ int g_cnt[NN];
__device__ int g_rowptr[NN + 1];
__device__ int g_blocksums[128];
__device__ int g_csr[EE];

// ---------------- helpers ----------------
__device__ __forceinline__ float lrelu_exp(float v) {
    float e = v > 0.0f ? v : 0.2f * v;
    return __expf(e);
}
__device__ __forceinline__ float warp_sum(float v) {
    #pragma unroll
    for (int o = 16; o > 0; o >>= 1) v += __shfl_xor_sync(0xffffffffu, v, o);
    return v;
}
__device__ __forceinline__ uint32_t smem_u32(const void* p) {
    uint32_t a;
    asm("{ .reg .u64 t; cvta.to.shared.u64 t, %1; cvt.u32.u64 %0, t; }" : "=r"(a) : "l"(p));
    return a;
}
__device__ __forceinline__ void ldsm4(uint32_t* r, uint32_t addr) {
    asm volatile("ldmatrix.sync.aligned.m8n8.x4.shared.b16 {%0,%1,%2,%3}, [%4];"
                 : "=r"(r[0]), "=r"(r[1]), "=r"(r[2]), "=r"(r[3]) : "r"(addr));
}
__device__ __forceinline__ void mma16816(float* c, const uint32_t* a, uint32_t b0, uint32_t b1) {
    asm volatile(
        "mma.sync.aligned.m16n8k16.row.col.f32.bf16.bf16.f32 "
        "{%0,%1,%2,%3}, {%4,%5,%6,%7}, {%8,%9}, {%0,%1,%2,%3};"
        : "+f"(c[0]), "+f"(c[1]), "+f"(c[2]), "+f"(c[3])
        : "r"(a[0]), "r"(a[1]), "r"(a[2]), "r"(a[3]), "r"(b0), "r"(b1));
}
__device__ __forceinline__ void cpa16(uint32_t smem, const void* g) {
    asm volatile("cp.async.cg.shared.global [%0], [%1], 16;" :: "r"(smem), "l"(g));
}
__device__ __forceinline__ void split_store(float v, __nv_bfloat16* hi, __nv_bfloat16* lo) {
    __nv_bfloat16 h = __float2bfloat16_rn(v);
    *hi = h;
    *lo = __float2bfloat16_rn(v - __bfloat162float(h));
}

// ---------------- prep_b: B images only (main stream) ------------------------------
__global__ void __launch_bounds__(256) prep_b(const float* __restrict__ W1,
                                              const float* __restrict__ resW,
                                              const float* __restrict__ W2) {
    int b = blockIdx.x, tid = threadIdx.x;
    if (b < 128) {
        int idx = b * 256 + tid;
        int nn = idx >> 7, k = idx & 127;
        float w = (nn < 128) ? W1[k * 128 + nn] : resW[k * 128 + (nn - 128)];
        split_store(w, &g_b1hi[nn * 128 + k], &g_b1lo[nn * 128 + k]);
    } else {
        int idx = (b - 128) * 256 + tid;
        int nn = idx >> 7, k = idx & 127;
        split_store(W2[k * 64 + nn], &g_b2hi[nn * 128 + k], &g_b2lo[nn * 128 + k]);
    }
}

__global__ void zero_cnt(int n) {
    int i = blockIdx.x * blockDim.x + threadIdx.x;
    if (i < n) g_cnt[i] = 0;
}

// ---------------- persistent-slab HMMA GEMM + fused att-dot epilogue ---------------
// A (fp32 [M][128]) loaded + hi/lo-split ONCE per CTA; loop NSLAB 64-col B slabs.
// MODE 1 (NSLAB=4): slabs 0,1 -> C0=h1 (+ att dots); slabs 2,3 -> C1=res
// MODE 2 (NSLAB=1): C0=h2 + single-head att dots via smem reduce
#define RS 136
#define A_ST (128 * RS)
#define B_ST (64 * RS)
#define SMEMB ((2 * A_ST + 2 * B_ST) * 2)   // 104448 bytes -> 2 CTAs/SM

template<int NSLAB, int MODE>
__global__ void __launch_bounds__(256) mma_gemm(const float* __restrict__ A,
                                                const __nv_bfloat16* __restrict__ Bhi,
                                                const __nv_bfloat16* __restrict__ Blo,
                                                float* __restrict__ C0,
                                                float* __restrict__ C1,
                                                const float* __restrict__ att_src,
                                                const float* __restrict__ att_dst,
                                                int M, int ldc) {
    extern __shared__ __nv_bfloat16 smp[];
    const uint32_t sb = smem_u32(smp);
    const uint32_t sbAh = sb, sbAl = sb + A_ST * 2;
    const uint32_t sbBh = sb + 2 * A_ST * 2, sbBl = sb + (2 * A_ST + B_ST) * 2;

    const int tid = threadIdx.x;
    const int wid = tid >> 5, lane = tid & 31;
    const int m0 = blockIdx.x * 128;

    auto issue_B = [&](int slab) {
        const __nv_bfloat16* bh = Bhi + (size_t)slab * 64 * 128;
        const __nv_bfloat16* bl = Blo + (size_t)slab * 64 * 128;
        #pragma unroll
        for (int it = 0; it < 4; it++) {
            int idx = tid + it * 256;
            int row = idx >> 4;
            int seg = (idx & 15) * 8;
            uint32_t so = (uint32_t)(row * RS + seg) * 2;
            cpa16(sbBh + so, bh + row * 128 + seg);
            cpa16(sbBl + so, bl + row * 128 + seg);
        }
        asm volatile("cp.async.commit_group;" ::: "memory");
    };

    issue_B(0);

    #pragma unroll
    for (int it = 0; it < 16; it++) {
        int idx = tid + it * 256;
        int row = idx >> 5;
        int colq = (idx & 31) * 4;
        float4 v = make_float4(0.f, 0.f, 0.f, 0.f);
        if (m0 + row < M) v = *(const float4*)(A + (size_t)(m0 + row) * 128 + colq);
        __nv_bfloat16 h0 = __float2bfloat16_rn(v.x), h1 = __float2bfloat16_rn(v.y);
        __nv_bfloat16 h2 = __float2bfloat16_rn(v.z), h3 = __float2bfloat16_rn(v.w);
        __nv_bfloat16 l0 = __float2bfloat16_rn(v.x - __bfloat162float(h0));
        __nv_bfloat16 l1 = __float2bfloat16_rn(v.y - __bfloat162float(h1));
        __nv_bfloat16 l2 = __float2bfloat16_rn(v.z - __bfloat162float(h2));
        __nv_bfloat16 l3 = __float2bfloat16_rn(v.w - __bfloat162float(h3));
        int o = row * RS + colq;
        *(__nv_bfloat162*)&smp[o]            = __halves2bfloat162(h0, h1);
        *(__nv_bfloat162*)&smp[o + 2]        = __halves2bfloat162(h2, h3);
        *(__nv_bfloat162*)&smp[A_ST + o]     = __halves2bfloat162(l0, l1);
        *(__nv_bfloat162*)&smp[A_ST + o + 2] = __halves2bfloat162(l2, l3);
    }
    asm volatile("cp.async.wait_group 0;" ::: "memory");
    __syncthreads();

    const int wm = wid >> 1;
    const int wn = wid & 1;

    #pragma unroll
    for (int slab = 0; slab < NSLAB; slab++) {
        float acc[2][4][4] = {};

        #pragma unroll
        for (int kk = 0; kk < 8; kk++) {
            uint32_t ah[2][4], alr[2][4];
            #pragma unroll
            for (int mt = 0; mt < 2; mt++) {
                uint32_t r = wm * 32 + mt * 16 + (lane & 15);
                uint32_t c = kk * 16 + (lane >> 4) * 8;
                uint32_t off = (r * RS + c) * 2;
                ldsm4(ah[mt], sbAh + off);
                ldsm4(alr[mt], sbAl + off);
            }
            uint32_t bh[2][4], bl[2][4];
            #pragma unroll
            for (int ld = 0; ld < 2; ld++) {
                uint32_t nrow = wn * 32 + ld * 16 + ((lane >> 4) & 1) * 8 + (lane & 7);
                uint32_t c = kk * 16 + ((lane >> 3) & 1) * 8;
                uint32_t off = (nrow * RS + c) * 2;
                ldsm4(bh[ld], sbBh + off);
                ldsm4(bl[ld], sbBl + off);
            }
            #pragma unroll
            for (int mt = 0; mt < 2; mt++)
                #pragma unroll
                for (int nt = 0; nt < 4; nt++) {
                    uint32_t b0h = bh[nt >> 1][(nt & 1) * 2], b1h = bh[nt >> 1][(nt & 1) * 2 + 1];
                    uint32_t b0l = bl[nt >> 1][(nt & 1) * 2], b1l = bl[nt >> 1][(nt & 1) * 2 + 1];
                    mma16816(acc[mt][nt], ah[mt], b0h, b1h);
                    mma16816(acc[mt][nt], ah[mt], b0l, b1l);
                    mma16816(acc[mt][nt], alr[mt], b0h, b1h);
                }
        }
        __syncthreads();
        if (slab + 1 < NSLAB) issue_B(slab + 1);

        // ---- per-slab C store ----
        float* Cp;
        int coloff;
        if (MODE == 2) { Cp = C0; coloff = 0; }
        else if (slab < 2) { Cp = C0; coloff = slab * 64; }
        else { Cp = C1; coloff = (slab - 2) * 64; }

        #pragma unroll
        for (int mt = 0; mt < 2; mt++)
            #pragma unroll
            for (int nt = 0; nt < 4; nt++) {
                int row = m0 + wm * 32 + mt * 16 + (lane >> 2);
                int col = coloff + wn * 32 + nt * 8 + (lane & 3) * 2;
                if (row < M)
                    *(float2*)&Cp[(size_t)row * ldc + col] = make_float2(acc[mt][nt][0], acc[mt][nt][1]);
                if (row + 8 < M)
                    *(float2*)&Cp[(size_t)(row + 8) * ldc + col] = make_float2(acc[mt][nt][2], acc[mt][nt][3]);
            }

        // ---- per-slab attention-dot epilogue ----
        if (MODE == 1 && slab < 2) {
            #pragma unroll
            for (int mt = 0; mt < 2; mt++) {
                #pragma unroll
                for (int hh = 0; hh < 2; hh++) {
                    int head = slab * 4 + wn * 2 + hh;
                    float ps0 = 0.f, pd0 = 0.f, ps1 = 0.f, pd1 = 0.f;
                    #pragma unroll
                    for (int q = 0; q < 2; q++) {
                        int nt = hh * 2 + q;
                        int cih = q * 8 + (lane & 3) * 2;
                        float a0 = att_src[head * 16 + cih], a1 = att_src[head * 16 + cih + 1];
                        float d0 = att_dst[head * 16 + cih], d1 = att_dst[head * 16 + cih + 1];
                        ps0 += acc[mt][nt][0] * a0 + acc[mt][nt][1] * a1;
                        pd0 += acc[mt][nt][0] * d0 + acc[mt][nt][1] * d1;
                        ps1 += acc[mt][nt][2] * a0 + acc[mt][nt][3] * a1;
                        pd1 += acc[mt][nt][2] * d0 + acc[mt][nt][3] * d1;
                    }
                    #pragma unroll
                    for (int o = 1; o <= 2; o <<= 1) {
                        ps0 += __shfl_xor_sync(0xffffffffu, ps0, o);
                        pd0 += __shfl_xor_sync(0xffffffffu, pd0, o);
                        ps1 += __shfl_xor_sync(0xffffffffu, ps1, o);
                        pd1 += __shfl_xor_sync(0xffffffffu, pd1, o);
                    }
                    if ((lane & 3) == 0) {
                        int r0 = m0 + wm * 32 + mt * 16 + (lane >> 2);
                        if (r0 < M)     { g_asrc1[r0 * 8 + head] = ps0;       g_adst1[r0 * 8 + head] = pd0; }
                        if (r0 + 8 < M) { g_asrc1[(r0 + 8) * 8 + head] = ps1; g_adst1[(r0 + 8) * 8 + head] = pd1; }
                    }
                }
            }
        }
        if (MODE == 2) {
            float* sps = (float*)smp;
            float* spd = sps + 256;
            float ps[2][2] = {}, pd[2][2] = {};
            #pragma unroll
            for (int nt = 0; nt < 4; nt++) {
                int col = wn * 32 + nt * 8 + (lane & 3) * 2;
                float a0 = att_src[col], a1 = att_src[col + 1];
                float d0 = att_dst[col], d1 = att_dst[col + 1];
                #pragma unroll
                for (int mt = 0; mt < 2; mt++) {
                    ps[mt][0] += acc[mt][nt][0] * a0 + acc[mt][nt][1] * a1;
                    pd[mt][0] += acc[mt][nt][0] * d0 + acc[mt][nt][1] * d1;
                    ps[mt][1] += acc[mt][nt][2] * a0 + acc[mt][nt][3] * a1;
                    pd[mt][1] += acc[mt][nt][2] * d0 + acc[mt][nt][3] * d1;
                }
            }
            #pragma unroll
            for (int o = 1; o <= 2; o <<= 1)
                #pragma unroll
                for (int mt = 0; mt < 2; mt++)
                    #pragma unroll
                    for (int hf = 0; hf < 2; hf++) {
                        ps[mt][hf] += __shfl_xor_sync(0xffffffffu, ps[mt][hf], o);
                        pd[mt][hf] += __shfl_xor_sync(0xffffffffu, pd[mt][hf], o);
                    }
            if ((lane & 3) == 0) {
                #pragma unroll
                for (int mt = 0; mt < 2; mt++)
                    #pragma unroll
                    for (int hf = 0; hf < 2; hf++) {
                        int rl = wm * 32 + mt * 16 + (lane >> 2) + hf * 8;
                        sps[rl * 2 + wn] = ps[mt][hf];
                        spd[rl * 2 + wn] = pd[mt][hf];
                    }
            }
            __syncthreads();
            if (tid < 128) {
                int r = m0 + tid;
                if (r < M) {
                    g_asrc2[r] = sps[tid * 2] + sps[tid * 2 + 1];
                    g_adst2[r] = spd[tid * 2] + spd[tid * 2 + 1];
                }
            }
        }

        if (slab + 1 < NSLAB) {
            asm volatile("cp.async.wait_group 0;" ::: "memory");
            __syncthreads();
        }
    }
}

// ---------------- CSR build --------------------------------------------------------
__global__ void count_k(const int* __restrict__ dst, int E) {
    int e = blockIdx.x * blockDim.x + threadIdx.x;
    if (e < E) atomicAdd(&g_cnt[dst[e]], 1);
}
__global__ void __launch_bounds__(1024) scan_blk(int n) {
    __shared__ int sm[1024];
    int tid = threadIdx.x;
    int i = blockIdx.x * 1024 + tid;
    int v = (i < n) ? g_cnt[i] : 0;
    sm[tid] = v;
    __syncthreads();
    #pragma unroll
    for (int off = 1; off < 1024; off <<= 1) {
        int t = (tid >= off) ? sm[tid - off] : 0;
        __syncthreads();
        sm[tid] += t;
        __syncthreads();
    }
    if (i < n) g_rowptr[i] = sm[tid] - v;
    if (tid == 1023) g_blocksums[blockIdx.x] = sm[1023];
}
__global__ void __launch_bounds__(128) scan_top(int nb) {
    __shared__ int sm[128];
    int tid = threadIdx.x;
    int v = (tid < nb) ? g_blocksums[tid] : 0;
    sm[tid] = v;
    __syncthreads();
    #pragma unroll
    for (int off = 1; off < 128; off <<= 1) {
        int t = (tid >= off) ? sm[tid - off] : 0;
        __syncthreads();
        sm[tid] += t;
        __syncthreads();
    }
    if (tid < nb) g_blocksums[tid] = sm[tid] - v;
}
__global__ void scan_add(int n, int E) {
    int i = blockIdx.x * blockDim.x + threadIdx.x;
    if (i < n) g_rowptr[i] += g_blocksums[i >> 10];
    if (i == 0) g_rowptr[n] = E;
}
__global__ void scatter_k(const int* __restrict__ src, const int* __restrict__ dst, int E) {
    int e = blockIdx.x * blockDim.x + threadIdx.x;
    if (e < E) {
        int d = dst[e];
        int old = atomicSub(&g_cnt[d], 1);
        g_csr[g_rowptr[d] + old - 1] = src[e];
    }
}

// ---------------- layer1 pull aggregation + finalize (warp per node) ---------------
__global__ void __launch_bounds__(256) agg_fin1(const float* __restrict__ bias1,
                                                const float* __restrict__ gamma,
                                                const float* __restrict__ beta,
                                                float* __restrict__ out, int n) {
    int i = (blockIdx.x * blockDim.x + threadIdx.x) >> 5;
    int lane = threadIdx.x & 31;
    if (i >= n) return;
    int head = lane >> 2;
    float ad = g_adst1[i * 8 + head];

    float4 acc;
    float denom;
    {
        float p = lrelu_exp(g_asrc1[i * 8 + head] + ad);
        float4 v = *(const float4*)&g_h1[(size_t)i * 128 + lane * 4];
        acc = make_float4(p * v.x, p * v.y, p * v.z, p * v.w);
        denom = p;
    }
    int start = g_rowptr[i], end = g_rowptr[i + 1];

    int j = start;
    // 8-wide unroll: deeper MLP for the gather stream
    for (; j + 8 <= end; j += 8) {
        int s[8];
        #pragma unroll
        for (int q = 0; q < 8; q++) s[q] = g_csr[j + q];
        float p[8];
        #pragma unroll
        for (int q = 0; q < 8; q++) p[q] = lrelu_exp(g_asrc1[s[q] * 8 + head] + ad);
        float4 v[8];
        #pragma unroll
        for (int q = 0; q < 8; q++) v[q] = *(const float4*)&g_h1[(size_t)s[q] * 128 + lane * 4];
        #pragma unroll
        for (int q = 0; q < 8; q++) {
            acc.x += p[q] * v[q].x; acc.y += p[q] * v[q].y;
            acc.z += p[q] * v[q].z; acc.w += p[q] * v[q].w;
            denom += p[q];
        }
    }
    for (; j + 4 <= end; j += 4) {
        int s0 = g_csr[j], s1 = g_csr[j + 1], s2 = g_csr[j + 2], s3 = g_csr[j + 3];
        float p0 = lrelu_exp(g_asrc1[s0 * 8 + head] + ad);
        float p1 = lrelu_exp(g_asrc1[s1 * 8 + head] + ad);
        float p2 = lrelu_exp(g_asrc1[s2 * 8 + head] + ad);
        float p3 = lrelu_exp(g_asrc1[s3 * 8 + head] + ad);
        float4 v0 = *(const float4*)&g_h1[(size_t)s0 * 128 + lane * 4];
        float4 v1 = *(const float4*)&g_h1[(size_t)s1 * 128 + lane * 4];
        float4 v2 = *(const float4*)&g_h1[(size_t)s2 * 128 + lane * 4];
        float4 v3 = *(const float4*)&g_h1[(size_t)s3 * 128 + lane * 4];
        acc.x += p0 * v0.x + p1 * v1.x + p2 * v2.x + p3 * v3.x;
        acc.y += p0 * v0.y + p1 * v1.y + p2 * v2.y + p3 * v3.y;
        acc.z += p0 * v0.z + p1 * v1.z + p2 * v2.z + p3 * v3.z;
        acc.w += p0 * v0.w + p1 * v1.w + p2 * v2.w + p3 * v3.w;
        denom += p0 + p1 + p2 + p3;
    }
    for (; j < end; j++) {
        int s = g_csr[j];
        float p = lrelu_exp(g_asrc1[s * 8 + head] + ad);
        float4 v = *(const float4*)&g_h1[(size_t)s * 128 + lane * 4];
        acc.x += p * v.x; acc.y += p * v.y; acc.z += p * v.z; acc.w += p * v.w;
        denom += p;
    }
    float inv = __fdividef(1.0f, denom + 1e-16f);
    float4 rv = *(const float4*)&g_res[(size_t)i * 128 + lane * 4];
    float4 bv = *(const float4*)&bias1[lane * 4];
    float4 v;
    v.x = acc.x * inv + bv.x + rv.x;
    v.y = acc.y * inv + bv.y + rv.y;
    v.z = acc.z * inv + bv.z + rv.z;
    v.w = acc.w * inv + bv.w + rv.w;
    float mu = warp_sum(v.x + v.y + v.z + v.w) * (1.0f / 128.0f);
    float dx = v.x - mu, dy = v.y - mu, dz = v.z - mu, dw = v.w - mu;
    float var = warp_sum(dx * dx + dy * dy + dz * dz + dw * dw) * (1.0f / 128.0f);
    float rs = rsqrtf(var + 1e-5f);
    float4 g4 = *(const float4*)&gamma[lane * 4];
    float4 b4 = *(const float4*)&beta[lane * 4];
    float4 o;
    o.x = dx * rs * g4.x + b4.x;
    o.y = dy * rs * g4.y + b4.y;
    o.z = dz * rs * g4.z + b4.z;
    o.w = dw * rs * g4.w + b4.w;
    o.x = o.x > 0.f ? o.x : expm1f(o.x);
    o.y = o.y > 0.f ? o.y : expm1f(o.y);
    o.z = o.z > 0.f ? o.z : expm1f(o.z);
    o.w = o.w > 0.f ? o.w : expm1f(o.w);
    *(float4*)(out + (size_t)i * 128 + lane * 4) = o;
}

// ---------------- layer2 pull aggregation + finalize (warp per node) ---------------
__global__ void __launch_bounds__(256) agg_fin2(const float* __restrict__ bias2,
                                                float* __restrict__ out, int n) {
    int i = (blockIdx.x * blockDim.x + threadIdx.x) >> 5;
    int lane = threadIdx.x & 31;
    if (i >= n) return;
    float ad = g_adst2[i];

    float2 acc;
    float denom;
    {
        float p = lrelu_exp(g_asrc2[i] + ad);
        float2 v = *(const float2*)&g_h2[(size_t)i * 64 + lane * 2];
        acc = make_float2(p * v.x, p * v.y);
        denom = p;
    }
    int start = g_rowptr[i], end = g_rowptr[i + 1];

    int j = start;
    for (; j + 8 <= end; j += 8) {
        int s[8];
        #pragma unroll
        for (int q = 0; q < 8; q++) s[q] = g_csr[j + q];
        float p[8];
        #pragma unroll
        for (int q = 0; q < 8; q++) p[q] = lrelu_exp(g_asrc2[s[q]] + ad);
        float2 v[8];
        #pragma unroll
        for (int q = 0; q < 8; q++) v[q] = *(const float2*)&g_h2[(size_t)s[q] * 64 + lane * 2];
        #pragma unroll
        for (int q = 0; q < 8; q++) {
            acc.x += p[q] * v[q].x; acc.y += p[q] * v[q].y;
            denom += p[q];
        }
    }
    for (; j + 4 <= end; j += 4) {
        int s0 = g_csr[j], s1 = g_csr[j + 1], s2 = g_csr[j + 2], s3 = g_csr[j + 3];
        float p0 = lrelu_exp(g_asrc2[s0] + ad);
        float p1 = lrelu_exp(g_asrc2[s1] + ad);
        float p2 = lrelu_exp(g_asrc2[s2] + ad);
        float p3 = lrelu_exp(g_asrc2[s3] + ad);
        float2 v0 = *(const float2*)&g_h2[(size_t)s0 * 64 + lane * 2];
        float2 v1 = *(const float2*)&g_h2[(size_t)s1 * 64 + lane * 2];
        float2 v2 = *(const float2*)&g_h2[(size_t)s2 * 64 + lane * 2];
        float2 v3 = *(const float2*)&g_h2[(size_t)s3 * 64 + lane * 2];
        acc.x += p0 * v0.x + p1 * v1.x + p2 * v2.x + p3 * v3.x;
        acc.y += p0 * v0.y + p1 * v1.y + p2 * v2.y + p3 * v3.y;
        denom += p0 + p1 + p2 + p3;
    }
    for (; j < end; j++) {
        int s = g_csr[j];
        float p = lrelu_exp(g_asrc2[s] + ad);
        float2 v = *(const float2*)&g_h2[(size_t)s * 64 + lane * 2];
        acc.x += p * v.x; acc.y += p * v.y;
        denom += p;
    }
    float inv = __fdividef(1.0f, denom + 1e-16f);
    float2 bv = *(const float2*)&bias2[lane * 2];
    float2 o;
    o.x = acc.x * inv + bv.x;
    o.y = acc.y * inv + bv.y;
    *(float2*)(out + (size_t)n * 128 + (size_t)i * 64 + lane * 2) = o;
}

// ---------------- launch (dual-stream: CSR build overlaps layer-1 GEMM) ------------
extern "C" void kernel_launch(void* const* d_in, const int* in_sizes, int n_in,
                              void* d_out, int out_size) {
    const float* x        = (const float*)d_in[0];
    const int*   ei       = (const int*)d_in[1];
    const float* W1       = (const float*)d_in[2];
    const float* att_src1 = (const float*)d_in[3];
    const float* att_dst1 = (const float*)d_in[4];
    const float* bias1    = (const float*)d_in[5];
    const float* res_W    = (const float*)d_in[6];
    const float* gamma    = (const float*)d_in[7];
    const float* beta     = (const float*)d_in[8];
    const float* W2       = (const float*)d_in[9];
    const float* att_src2 = (const float*)d_in[10];
    const float* att_dst2 = (const float*)d_in[11];
    const float* bias2    = (const float*)d_in[12];
    float* out = (float*)d_out;

    int n = in_sizes[0] / 128;
    int E = in_sizes[1] / 2;
    if (n > NN) n = NN;
    if (E > EE) E = EE;
    const int* srcp = ei;
    const int* dstp = ei + E;

    float *p_h1, *p_res, *p_h2;
    __nv_bfloat16 *b1h, *b1l, *b2h, *b2l;
    cudaGetSymbolAddress((void**)&p_h1, g_h1);
    cudaGetSymbolAddress((void**)&p_res, g_res);
    cudaGetSymbolAddress((void**)&p_h2, g_h2);
    cudaGetSymbolAddress((void**)&b1h, g_b1hi);
    cudaGetSymbolAddress((void**)&b1l, g_b1lo);
    cudaGetSymbolAddress((void**)&b2h, g_b2hi);
    cudaGetSymbolAddress((void**)&b2l, g_b2lo);

    cudaFuncSetAttribute(mma_gemm<4, 1>, cudaFuncAttributeMaxDynamicSharedMemorySize, SMEMB);
    cudaFuncSetAttribute(mma_gemm<1, 2>, cudaFuncAttributeMaxDynamicSharedMemorySize, SMEMB);

    int nb = (n + 1023) / 1024;
    int mblocks = (n + 127) / 128;
    int nwarp_blocks = (n + 7) / 8;

    cudaStream_t s2;
    cudaEvent_t evFork, evJoin;
    cudaStreamCreateWithFlags(&s2, cudaStreamNonBlocking);
    cudaEventCreateWithFlags(&evFork, cudaEventDisableTiming);
    cudaEventCreateWithFlags(&evJoin, cudaEventDisableTiming);

    // ---- fork at t=0 ----
    cudaEventRecord(evFork, 0);
    cudaStreamWaitEvent(s2, evFork, 0);

    // side stream: full CSR chain (incl. zeroing)
    zero_cnt<<<(n + 255) / 256, 256, 0, s2>>>(n);
    count_k<<<(E + 255) / 256, 256, 0, s2>>>(dstp, E);
    scan_blk<<<nb, 1024, 0, s2>>>(n);
    scan_top<<<1, 128, 0, s2>>>(nb);
    scan_add<<<(n + 255) / 256, 256, 0, s2>>>(n, E);
    scatter_k<<<(E + 255) / 256, 256, 0, s2>>>(srcp, dstp, E);
    cudaEventRecord(evJoin, s2);

    // main stream: B images + layer-1 persistent-slab HMMA GEMM
    prep_b<<<160, 256>>>(W1, res_W, W2);
    mma_gemm<4, 1><<<mblocks, 256, SMEMB>>>(x, b1h, b1l, p_h1, p_res,
                                            att_src1, att_dst1, n, 128);

    // join: aggregation needs CSR too
    cudaStreamWaitEvent(0, evJoin, 0);

    // layer-1 aggregation + LN + ELU
    agg_fin1<<<nwarp_blocks, 256>>>(bias1, gamma, beta, out, n);
    // layer-2 HMMA GEMM + att dots
    mma_gemm<1, 2><<<mblocks, 256, SMEMB>>>(out, b2h, b2l, p_h2, nullptr,
                                            att_src2, att_dst2, n, 64);
    // layer-2 aggregation -> logits
    agg_fin2<<<nwarp_blocks, 256>>>(bias2, out, n);
}

// round 17
// speedup vs baseline: 1.4128x; 1.0353x over previous
#include <cuda_runtime.h>
#include <cuda_bf16.h>
#include <math.h>
#include <stdint.h>

#define NN 100000
#define EE 1600000

// ---------------- static scratch ----------------
__device__ float g_h1[NN * 128];
__device__ float g_res[NN * 128];
__device__ float g_asrc1[NN * 8];
__device__ float g_adst1[NN * 8];
__device__ float g_h2[NN * 64];
__device__ float g_asrc2[NN];
__device__ float g_adst2[NN];
__device__ __nv_bfloat16 g_b1hi[256 * 128];
__device__ __nv_bfloat16 g_b1lo[256 * 128];
__device__ __nv_bfloat16 g_b2hi[64 * 128];
__device__ __nv_bfloat16 g_b2lo[64 * 128];
__device__ int g_cnt[NN];
__device__ int g_rowptr[NN + 1];
__device__ int g_blocksums[128];
__device__ int g_csr[EE];

// ---------------- helpers ----------------
__device__ __forceinline__ float lrelu_exp(float v) {
    float e = v > 0.0f ? v : 0.2f * v;
    return __expf(e);
}
__device__ __forceinline__ float warp_sum(float v) {
    #pragma unroll
    for (int o = 16; o > 0; o >>= 1) v += __shfl_xor_sync(0xffffffffu, v, o);
    return v;
}
__device__ __forceinline__ uint32_t smem_u32(const void* p) {
    uint32_t a;
    asm("{ .reg .u64 t; cvta.to.shared.u64 t, %1; cvt.u32.u64 %0, t; }" : "=r"(a) : "l"(p));
    return a;
}
__device__ __forceinline__ void ldsm4(uint32_t* r, uint32_t addr) {
    asm volatile("ldmatrix.sync.aligned.m8n8.x4.shared.b16 {%0,%1,%2,%3}, [%4];"
                 : "=r"(r[0]), "=r"(r[1]), "=r"(r[2]), "=r"(r[3]) : "r"(addr));
}
__device__ __forceinline__ void mma16816(float* c, const uint32_t* a, uint32_t b0, uint32_t b1) {
    asm volatile(
        "mma.sync.aligned.m16n8k16.row.col.f32.bf16.bf16.f32 "
        "{%0,%1,%2,%3}, {%4,%5,%6,%7}, {%8,%9}, {%0,%1,%2,%3};"
        : "+f"(c[0]), "+f"(c[1]), "+f"(c[2]), "+f"(c[3])
        : "r"(a[0]), "r"(a[1]), "r"(a[2]), "r"(a[3]), "r"(b0), "r"(b1));
}
__device__ __forceinline__ void cpa16(uint32_t smem, const void* g) {
    asm volatile("cp.async.cg.shared.global [%0], [%1], 16;" :: "r"(smem), "l"(g));
}
__device__ __forceinline__ void split_store(float v, __nv_bfloat16* hi, __nv_bfloat16* lo) {
    __nv_bfloat16 h = __float2bfloat16_rn(v);
    *hi = h;
    *lo = __float2bfloat16_rn(v - __bfloat162float(h));
}

// ---------------- prep_b: B images only (main stream) ------------------------------
__global__ void __launch_bounds__(256) prep_b(const float* __restrict__ W1,
                                              const float* __restrict__ resW,
                                              const float* __restrict__ W2) {
    int b = blockIdx.x, tid = threadIdx.x;
    if (b < 128) {
        int idx = b * 256 + tid;
        int nn = idx >> 7, k = idx & 127;
        float w = (nn < 128) ? W1[k * 128 + nn] : resW[k * 128 + (nn - 128)];
        split_store(w, &g_b1hi[nn * 128 + k], &g_b1lo[nn * 128 + k]);
    } else {
        int idx = (b - 128) * 256 + tid;
        int nn = idx >> 7, k = idx & 127;
        split_store(W2[k * 64 + nn], &g_b2hi[nn * 128 + k], &g_b2lo[nn * 128 + k]);
    }
}

__global__ void zero_cnt(int n) {
    int i = blockIdx.x * blockDim.x + threadIdx.x;
    if (i < n) g_cnt[i] = 0;
}

// ---------------- persistent-slab HMMA GEMM + fused att-dot epilogue ---------------
// A (fp32 [M][128]) loaded + hi/lo-split ONCE per CTA; loop NSLAB 64-col B slabs.
// MODE 1 (NSLAB=4): slabs 0,1 -> C0=h1 (+ att dots); slabs 2,3 -> C1=res
// MODE 2 (NSLAB=1): C0=h2 + single-head att dots via smem reduce
// bOff: row-block offset (for split launches).
#define RS 136
#define A_ST (128 * RS)
#define B_ST (64 * RS)
#define SMEMB ((2 * A_ST + 2 * B_ST) * 2)   // 104448 bytes -> 2 CTAs/SM

template<int NSLAB, int MODE>
__global__ void __launch_bounds__(256) mma_gemm(const float* __restrict__ A,
                                                const __nv_bfloat16* __restrict__ Bhi,
                                                const __nv_bfloat16* __restrict__ Blo,
                                                float* __restrict__ C0,
                                                float* __restrict__ C1,
                                                const float* __restrict__ att_src,
                                                const float* __restrict__ att_dst,
                                                int M, int ldc, int bOff) {
    extern __shared__ __nv_bfloat16 smp[];
    const uint32_t sb = smem_u32(smp);
    const uint32_t sbAh = sb, sbAl = sb + A_ST * 2;
    const uint32_t sbBh = sb + 2 * A_ST * 2, sbBl = sb + (2 * A_ST + B_ST) * 2;

    const int tid = threadIdx.x;
    const int wid = tid >> 5, lane = tid & 31;
    const int m0 = (blockIdx.x + bOff) * 128;

    auto issue_B = [&](int slab) {
        const __nv_bfloat16* bh = Bhi + (size_t)slab * 64 * 128;
        const __nv_bfloat16* bl = Blo + (size_t)slab * 64 * 128;
        #pragma unroll
        for (int it = 0; it < 4; it++) {
            int idx = tid + it * 256;
            int row = idx >> 4;
            int seg = (idx & 15) * 8;
            uint32_t so = (uint32_t)(row * RS + seg) * 2;
            cpa16(sbBh + so, bh + row * 128 + seg);
            cpa16(sbBl + so, bl + row * 128 + seg);
        }
        asm volatile("cp.async.commit_group;" ::: "memory");
    };

    issue_B(0);

    #pragma unroll
    for (int it = 0; it < 16; it++) {
        int idx = tid + it * 256;
        int row = idx >> 5;
        int colq = (idx & 31) * 4;
        float4 v = make_float4(0.f, 0.f, 0.f, 0.f);
        if (m0 + row < M) v = *(const float4*)(A + (size_t)(m0 + row) * 128 + colq);
        __nv_bfloat16 h0 = __float2bfloat16_rn(v.x), h1 = __float2bfloat16_rn(v.y);
        __nv_bfloat16 h2 = __float2bfloat16_rn(v.z), h3 = __float2bfloat16_rn(v.w);
        __nv_bfloat16 l0 = __float2bfloat16_rn(v.x - __bfloat162float(h0));
        __nv_bfloat16 l1 = __float2bfloat16_rn(v.y - __bfloat162float(h1));
        __nv_bfloat16 l2 = __float2bfloat16_rn(v.z - __bfloat162float(h2));
        __nv_bfloat16 l3 = __float2bfloat16_rn(v.w - __bfloat162float(h3));
        int o = row * RS + colq;
        *(__nv_bfloat162*)&smp[o]            = __halves2bfloat162(h0, h1);
        *(__nv_bfloat162*)&smp[o + 2]        = __halves2bfloat162(h2, h3);
        *(__nv_bfloat162*)&smp[A_ST + o]     = __halves2bfloat162(l0, l1);
        *(__nv_bfloat162*)&smp[A_ST + o + 2] = __halves2bfloat162(l2, l3);
    }
    asm volatile("cp.async.wait_group 0;" ::: "memory");
    __syncthreads();

    const int wm = wid >> 1;
    const int wn = wid & 1;

    #pragma unroll
    for (int slab = 0; slab < NSLAB; slab++) {
        float acc[2][4][4] = {};

        #pragma unroll
        for (int kk = 0; kk < 8; kk++) {
            uint32_t ah[2][4], alr[2][4];
            #pragma unroll
            for (int mt = 0; mt < 2; mt++) {
                uint32_t r = wm * 32 + mt * 16 + (lane & 15);
                uint32_t c = kk * 16 + (lane >> 4) * 8;
                uint32_t off = (r * RS + c) * 2;
                ldsm4(ah[mt], sbAh + off);
                ldsm4(alr[mt], sbAl + off);
            }
            uint32_t bh[2][4], bl[2][4];
            #pragma unroll
            for (int ld = 0; ld < 2; ld++) {
                uint32_t nrow = wn * 32 + ld * 16 + ((lane >> 4) & 1) * 8 + (lane & 7);
                uint32_t c = kk * 16 + ((lane >> 3) & 1) * 8;
                uint32_t off = (nrow * RS + c) * 2;
                ldsm4(bh[ld], sbBh + off);
                ldsm4(bl[ld], sbBl + off);
            }
            #pragma unroll
            for (int mt = 0; mt < 2; mt++)
                #pragma unroll
                for (int nt = 0; nt < 4; nt++) {
                    uint32_t b0h = bh[nt >> 1][(nt & 1) * 2], b1h = bh[nt >> 1][(nt & 1) * 2 + 1];
                    uint32_t b0l = bl[nt >> 1][(nt & 1) * 2], b1l = bl[nt >> 1][(nt & 1) * 2 + 1];
                    mma16816(acc[mt][nt], ah[mt], b0h, b1h);
                    mma16816(acc[mt][nt], ah[mt], b0l, b1l);
                    mma16816(acc[mt][nt], alr[mt], b0h, b1h);
                }
        }
        __syncthreads();
        if (slab + 1 < NSLAB) issue_B(slab + 1);

        // ---- per-slab C store ----
        float* Cp;
        int coloff;
        if (MODE == 2) { Cp = C0; coloff = 0; }
        else if (slab < 2) { Cp = C0; coloff = slab * 64; }
        else { Cp = C1; coloff = (slab - 2) * 64; }

        #pragma unroll
        for (int mt = 0; mt < 2; mt++)
            #pragma unroll
            for (int nt = 0; nt < 4; nt++) {
                int row = m0 + wm * 32 + mt * 16 + (lane >> 2);
                int col = coloff + wn * 32 + nt * 8 + (lane & 3) * 2;
                if (row < M)
                    *(float2*)&Cp[(size_t)row * ldc + col] = make_float2(acc[mt][nt][0], acc[mt][nt][1]);
                if (row + 8 < M)
                    *(float2*)&Cp[(size_t)(row + 8) * ldc + col] = make_float2(acc[mt][nt][2], acc[mt][nt][3]);
            }

        // ---- per-slab attention-dot epilogue ----
        if (MODE == 1 && slab < 2) {
            #pragma unroll
            for (int mt = 0; mt < 2; mt++) {
                #pragma unroll
                for (int hh = 0; hh < 2; hh++) {
                    int head = slab * 4 + wn * 2 + hh;
                    float ps0 = 0.f, pd0 = 0.f, ps1 = 0.f, pd1 = 0.f;
                    #pragma unroll
                    for (int q = 0; q < 2; q++) {
                        int nt = hh * 2 + q;
                        int cih = q * 8 + (lane & 3) * 2;
                        float a0 = att_src[head * 16 + cih], a1 = att_src[head * 16 + cih + 1];
                        float d0 = att_dst[head * 16 + cih], d1 = att_dst[head * 16 + cih + 1];
                        ps0 += acc[mt][nt][0] * a0 + acc[mt][nt][1] * a1;
                        pd0 += acc[mt][nt][0] * d0 + acc[mt][nt][1] * d1;
                        ps1 += acc[mt][nt][2] * a0 + acc[mt][nt][3] * a1;
                        pd1 += acc[mt][nt][2] * d0 + acc[mt][nt][3] * d1;
                    }
                    #pragma unroll
                    for (int o = 1; o <= 2; o <<= 1) {
                        ps0 += __shfl_xor_sync(0xffffffffu, ps0, o);
                        pd0 += __shfl_xor_sync(0xffffffffu, pd0, o);
                        ps1 += __shfl_xor_sync(0xffffffffu, ps1, o);
                        pd1 += __shfl_xor_sync(0xffffffffu, pd1, o);
                    }
                    if ((lane & 3) == 0) {
                        int r0 = m0 + wm * 32 + mt * 16 + (lane >> 2);
                        if (r0 < M)     { g_asrc1[r0 * 8 + head] = ps0;       g_adst1[r0 * 8 + head] = pd0; }
                        if (r0 + 8 < M) { g_asrc1[(r0 + 8) * 8 + head] = ps1; g_adst1[(r0 + 8) * 8 + head] = pd1; }
                    }
                }
            }
        }
        if (MODE == 2) {
            float* sps = (float*)smp;
            float* spd = sps + 256;
            float ps[2][2] = {}, pd[2][2] = {};
            #pragma unroll
            for (int nt = 0; nt < 4; nt++) {
                int col = wn * 32 + nt * 8 + (lane & 3) * 2;
                float a0 = att_src[col], a1 = att_src[col + 1];
                float d0 = att_dst[col], d1 = att_dst[col + 1];
                #pragma unroll
                for (int mt = 0; mt < 2; mt++) {
                    ps[mt][0] += acc[mt][nt][0] * a0 + acc[mt][nt][1] * a1;
                    pd[mt][0] += acc[mt][nt][0] * d0 + acc[mt][nt][1] * d1;
                    ps[mt][1] += acc[mt][nt][2] * a0 + acc[mt][nt][3] * a1;
                    pd[mt][1] += acc[mt][nt][2] * d0 + acc[mt][nt][3] * d1;
                }
            }
            #pragma unroll
            for (int o = 1; o <= 2; o <<= 1)
                #pragma unroll
                for (int mt = 0; mt < 2; mt++)
                    #pragma unroll
                    for (int hf = 0; hf < 2; hf++) {
                        ps[mt][hf] += __shfl_xor_sync(0xffffffffu, ps[mt][hf], o);
                        pd[mt][hf] += __shfl_xor_sync(0xffffffffu, pd[mt][hf], o);
                    }
            if ((lane & 3) == 0) {
                #pragma unroll
                for (int mt = 0; mt < 2; mt++)
                    #pragma unroll
                    for (int hf = 0; hf < 2; hf++) {
                        int rl = wm * 32 + mt * 16 + (lane >> 2) + hf * 8;
                        sps[rl * 2 + wn] = ps[mt][hf];
                        spd[rl * 2 + wn] = pd[mt][hf];
                    }
            }
            __syncthreads();
            if (tid < 128) {
                int r = m0 + tid;
                if (r < M) {
                    g_asrc2[r] = sps[tid * 2] + sps[tid * 2 + 1];
                    g_adst2[r] = spd[tid * 2] + spd[tid * 2 + 1];
                }
            }
        }

        if (slab + 1 < NSLAB) {
            asm volatile("cp.async.wait_group 0;" ::: "memory");
            __syncthreads();
        }
    }
}

// ---------------- CSR build --------------------------------------------------------
__global__ void count_k(const int* __restrict__ dst, int E) {
    int e = blockIdx.x * blockDim.x + threadIdx.x;
    if (e < E) atomicAdd(&g_cnt[dst[e]], 1);
}
__global__ void __launch_bounds__(1024) scan_blk(int n) {
    __shared__ int sm[1024];
    int tid = threadIdx.x;
    int i = blockIdx.x * 1024 + tid;
    int v = (i < n) ? g_cnt[i] : 0;
    sm[tid] = v;
    __syncthreads();
    #pragma unroll
    for (int off = 1; off < 1024; off <<= 1) {
        int t = (tid >= off) ? sm[tid - off] : 0;
        __syncthreads();
        sm[tid] += t;
        __syncthreads();
    }
    if (i < n) g_rowptr[i] = sm[tid] - v;
    if (tid == 1023) g_blocksums[blockIdx.x] = sm[1023];
}
__global__ void __launch_bounds__(128) scan_top(int nb) {
    __shared__ int sm[128];
    int tid = threadIdx.x;
    int v = (tid < nb) ? g_blocksums[tid] : 0;
    sm[tid] = v;
    __syncthreads();
    #pragma unroll
    for (int off = 1; off < 128; off <<= 1) {
        int t = (tid >= off) ? sm[tid - off] : 0;
        __syncthreads();
        sm[tid] += t;
        __syncthreads();
    }
    if (tid < nb) g_blocksums[tid] = sm[tid] - v;
}
__global__ void scan_add(int n, int E) {
    int i = blockIdx.x * blockDim.x + threadIdx.x;
    if (i < n) g_rowptr[i] += g_blocksums[i >> 10];
    if (i == 0) g_rowptr[n] = E;
}
__global__ void scatter_k(const int* __restrict__ src, const int* __restrict__ dst, int E) {
    int e = blockIdx.x * blockDim.x + threadIdx.x;
    if (e < E) {
        int d = dst[e];
        int old = atomicSub(&g_cnt[d], 1);
        g_csr[g_rowptr[d] + old - 1] = src[e];
    }
}

// ---------------- layer1 pull aggregation + finalize (warp per node) ---------------
// processes nodes [i0, i0 + 32*gridDim.x*blocks...) intersect [0, n)
__global__ void __launch_bounds__(256) agg_fin1(const float* __restrict__ bias1,
                                                const float* __restrict__ gamma,
                                                const float* __restrict__ beta,
                                                float* __restrict__ out,
                                                int i0, int iend) {
    int i = i0 + ((blockIdx.x * blockDim.x + threadIdx.x) >> 5);
    int lane = threadIdx.x & 31;
    if (i >= iend) return;
    int head = lane >> 2;
    float ad = g_adst1[i * 8 + head];

    float4 acc;
    float denom;
    {
        float p = lrelu_exp(g_asrc1[i * 8 + head] + ad);
        float4 v = *(const float4*)&g_h1[(size_t)i * 128 + lane * 4];
        acc = make_float4(p * v.x, p * v.y, p * v.z, p * v.w);
        denom = p;
    }
    int start = g_rowptr[i], end = g_rowptr[i + 1];

    int j = start;
    for (; j + 4 <= end; j += 4) {
        int s0 = g_csr[j], s1 = g_csr[j + 1], s2 = g_csr[j + 2], s3 = g_csr[j + 3];
        float p0 = lrelu_exp(g_asrc1[s0 * 8 + head] + ad);
        float p1 = lrelu_exp(g_asrc1[s1 * 8 + head] + ad);
        float p2 = lrelu_exp(g_asrc1[s2 * 8 + head] + ad);
        float p3 = lrelu_exp(g_asrc1[s3 * 8 + head] + ad);
        float4 v0 = *(const float4*)&g_h1[(size_t)s0 * 128 + lane * 4];
        float4 v1 = *(const float4*)&g_h1[(size_t)s1 * 128 + lane * 4];
        float4 v2 = *(const float4*)&g_h1[(size_t)s2 * 128 + lane * 4];
        float4 v3 = *(const float4*)&g_h1[(size_t)s3 * 128 + lane * 4];
        acc.x += p0 * v0.x + p1 * v1.x + p2 * v2.x + p3 * v3.x;
        acc.y += p0 * v0.y + p1 * v1.y + p2 * v2.y + p3 * v3.y;
        acc.z += p0 * v0.z + p1 * v1.z + p2 * v2.z + p3 * v3.z;
        acc.w += p0 * v0.w + p1 * v1.w + p2 * v2.w + p3 * v3.w;
        denom += p0 + p1 + p2 + p3;
    }
    for (; j < end; j++) {
        int s = g_csr[j];
        float p = lrelu_exp(g_asrc1[s * 8 + head] + ad);
        float4 v = *(const float4*)&g_h1[(size_t)s * 128 + lane * 4];
        acc.x += p * v.x; acc.y += p * v.y; acc.z += p * v.z; acc.w += p * v.w;
        denom += p;
    }
    float inv = __fdividef(1.0f, denom + 1e-16f);
    float4 rv = *(const float4*)&g_res[(size_t)i * 128 + lane * 4];
    float4 bv = *(const float4*)&bias1[lane * 4];
    float4 v;
    v.x = acc.x * inv + bv.x + rv.x;
    v.y = acc.y * inv + bv.y + rv.y;
    v.z = acc.z * inv + bv.z + rv.z;
    v.w = acc.w * inv + bv.w + rv.w;
    float mu = warp_sum(v.x + v.y + v.z + v.w) * (1.0f / 128.0f);
    float dx = v.x - mu, dy = v.y - mu, dz = v.z - mu, dw = v.w - mu;
    float var = warp_sum(dx * dx + dy * dy + dz * dz + dw * dw) * (1.0f / 128.0f);
    float rs = rsqrtf(var + 1e-5f);
    float4 g4 = *(const float4*)&gamma[lane * 4];
    float4 b4 = *(const float4*)&beta[lane * 4];
    float4 o;
    o.x = dx * rs * g4.x + b4.x;
    o.y = dy * rs * g4.y + b4.y;
    o.z = dz * rs * g4.z + b4.z;
    o.w = dw * rs * g4.w + b4.w;
    o.x = o.x > 0.f ? o.x : expm1f(o.x);
    o.y = o.y > 0.f ? o.y : expm1f(o.y);
    o.z = o.z > 0.f ? o.z : expm1f(o.z);
    o.w = o.w > 0.f ? o.w : expm1f(o.w);
    *(float4*)(out + (size_t)i * 128 + lane * 4) = o;
}

// ---------------- layer2 pull aggregation + finalize (warp per node) ---------------
__global__ void __launch_bounds__(256) agg_fin2(const float* __restrict__ bias2,
                                                float* __restrict__ out, int n) {
    int i = (blockIdx.x * blockDim.x + threadIdx.x) >> 5;
    int lane = threadIdx.x & 31;
    if (i >= n) return;
    float ad = g_adst2[i];

    float2 acc;
    float denom;
    {
        float p = lrelu_exp(g_asrc2[i] + ad);
        float2 v = *(const float2*)&g_h2[(size_t)i * 64 + lane * 2];
        acc = make_float2(p * v.x, p * v.y);
        denom = p;
    }
    int start = g_rowptr[i], end = g_rowptr[i + 1];

    int j = start;
    for (; j + 4 <= end; j += 4) {
        int s0 = g_csr[j], s1 = g_csr[j + 1], s2 = g_csr[j + 2], s3 = g_csr[j + 3];
        float p0 = lrelu_exp(g_asrc2[s0] + ad);
        float p1 = lrelu_exp(g_asrc2[s1] + ad);
        float p2 = lrelu_exp(g_asrc2[s2] + ad);
        float p3 = lrelu_exp(g_asrc2[s3] + ad);
        float2 v0 = *(const float2*)&g_h2[(size_t)s0 * 64 + lane * 2];
        float2 v1 = *(const float2*)&g_h2[(size_t)s1 * 64 + lane * 2];
        float2 v2 = *(const float2*)&g_h2[(size_t)s2 * 64 + lane * 2];
        float2 v3 = *(const float2*)&g_h2[(size_t)s3 * 64 + lane * 2];
        acc.x += p0 * v0.x + p1 * v1.x + p2 * v2.x + p3 * v3.x;
        acc.y += p0 * v0.y + p1 * v1.y + p2 * v2.y + p3 * v3.y;
        denom += p0 + p1 + p2 + p3;
    }
    for (; j < end; j++) {
        int s = g_csr[j];
        float p = lrelu_exp(g_asrc2[s] + ad);
        float2 v = *(const float2*)&g_h2[(size_t)s * 64 + lane * 2];
        acc.x += p * v.x; acc.y += p * v.y;
        denom += p;
    }
    float inv = __fdividef(1.0f, denom + 1e-16f);
    float2 bv = *(const float2*)&bias2[lane * 2];
    float2 o;
    o.x = acc.x * inv + bv.x;
    o.y = acc.y * inv + bv.y;
    *(float2*)(out + (size_t)n * 128 + (size_t)i * 64 + lane * 2) = o;
}

// ---------------- launch (dual-stream; layer-2 GEMM pipelined with agg) ------------
extern "C" void kernel_launch(void* const* d_in, const int* in_sizes, int n_in,
                              void* d_out, int out_size) {
    const float* x        = (const float*)d_in[0];
    const int*   ei       = (const int*)d_in[1];
    const float* W1       = (const float*)d_in[2];
    const float* att_src1 = (const float*)d_in[3];
    const float* att_dst1 = (const float*)d_in[4];
    const float* bias1    = (const float*)d_in[5];
    const float* res_W    = (const float*)d_in[6];
    const float* gamma    = (const float*)d_in[7];
    const float* beta     = (const float*)d_in[8];
    const float* W2       = (const float*)d_in[9];
    const float* att_src2 = (const float*)d_in[10];
    const float* att_dst2 = (const float*)d_in[11];
    const float* bias2    = (const float*)d_in[12];
    float* out = (float*)d_out;

    int n = in_sizes[0] / 128;
    int E = in_sizes[1] / 2;
    if (n > NN) n = NN;
    if (E > EE) E = EE;
    const int* srcp = ei;
    const int* dstp = ei + E;

    float *p_h1, *p_res, *p_h2;
    __nv_bfloat16 *b1h, *b1l, *b2h, *b2l;
    cudaGetSymbolAddress((void**)&p_h1, g_h1);
    cudaGetSymbolAddress((void**)&p_res, g_res);
    cudaGetSymbolAddress((void**)&p_h2, g_h2);
    cudaGetSymbolAddress((void**)&b1h, g_b1hi);
    cudaGetSymbolAddress((void**)&b1l, g_b1lo);
    cudaGetSymbolAddress((void**)&b2h, g_b2hi);
    cudaGetSymbolAddress((void**)&b2l, g_b2lo);

    cudaFuncSetAttribute(mma_gemm<4, 1>, cudaFuncAttributeMaxDynamicSharedMemorySize, SMEMB);
    cudaFuncSetAttribute(mma_gemm<1, 2>, cudaFuncAttributeMaxDynamicSharedMemorySize, SMEMB);

    int nb = (n + 1023) / 1024;
    int mblocks = (n + 127) / 128;
    int nwarp_blocks = (n + 7) / 8;

    // split for layer-2 pipelining
    int mb0 = (mblocks + 1) / 2;          // first-half row blocks
    int mb1 = mblocks - mb0;
    int n0 = mb0 * 128;                    // first-half node count (multiple of 128)
    if (n0 > n) n0 = n;
    int wb0 = (n0 + 7) / 8;                // agg_fin1 part0 blocks
    int wb1 = (n - n0 + 7) / 8;

    cudaStream_t s2;
    cudaEvent_t evFork, evJoin, evA0, evG0;
    cudaStreamCreateWithFlags(&s2, cudaStreamNonBlocking);
    cudaEventCreateWithFlags(&evFork, cudaEventDisableTiming);
    cudaEventCreateWithFlags(&evJoin, cudaEventDisableTiming);
    cudaEventCreateWithFlags(&evA0, cudaEventDisableTiming);
    cudaEventCreateWithFlags(&evG0, cudaEventDisableTiming);

    // ---- fork at t=0: CSR build on s2 ----
    cudaEventRecord(evFork, 0);
    cudaStreamWaitEvent(s2, evFork, 0);
    zero_cnt<<<(n + 255) / 256, 256, 0, s2>>>(n);
    count_k<<<(E + 255) / 256, 256, 0, s2>>>(dstp, E);
    scan_blk<<<nb, 1024, 0, s2>>>(n);
    scan_top<<<1, 128, 0, s2>>>(nb);
    scan_add<<<(n + 255) / 256, 256, 0, s2>>>(n, E);
    scatter_k<<<(E + 255) / 256, 256, 0, s2>>>(srcp, dstp, E);
    cudaEventRecord(evJoin, s2);

    // main: B images + layer-1 GEMM
    prep_b<<<160, 256>>>(W1, res_W, W2);
    mma_gemm<4, 1><<<mblocks, 256, SMEMB>>>(x, b1h, b1l, p_h1, p_res,
                                            att_src1, att_dst1, n, 128, 0);

    // join CSR before aggregation
    cudaStreamWaitEvent(0, evJoin, 0);

    // ---- layer-1 aggregation part 0 (nodes [0, n0)) ----
    agg_fin1<<<wb0, 256>>>(bias1, gamma, beta, out, 0, n0);
    cudaEventRecord(evA0, 0);

    // side stream: layer-2 GEMM on first-half rows, overlapped with agg part 1
    cudaStreamWaitEvent(s2, evA0, 0);
    mma_gemm<1, 2><<<mb0, 256, SMEMB, s2>>>(out, b2h, b2l, p_h2, nullptr,
                                            att_src2, att_dst2, n, 64, 0);
    cudaEventRecord(evG0, s2);

    // main: layer-1 aggregation part 1 (nodes [n0, n))
    if (wb1 > 0)
        agg_fin1<<<wb1, 256>>>(bias1, gamma, beta, out, n0, n);
    // main: layer-2 GEMM on second-half rows
    if (mb1 > 0)
        mma_gemm<1, 2><<<mb1, 256, SMEMB>>>(out, b2h, b2l, p_h2, nullptr,
                                            att_src2, att_dst2, n, 64, mb0);
    // join side-stream gemm2 part 0
    cudaStreamWaitEvent(0, evG0, 0);

    // layer-2 aggregation -> logits
    agg_fin2<<<nwarp_blocks, 256>>>(bias2, out, n);
}